// round 13
// baseline (speedup 1.0000x reference)
#include <cuda_runtime.h>
#include <cuda_fp16.h>
#include <cstdint>

#define D       256
#define KNBR    16
#define MAXN    50000
#define LN_EPS  1e-5f
#define TILE_M  64
#define KCH     32
#define NCH     8          // K chunks
#define ROWP    40         // row pitch in fp16 elems (80 B) -> conflict-free ldmatrix

// ---------------- scratch (static device arrays; no allocations) ------------
__device__ __half feat16[(size_t)MAXN * D];   // fp16 features (25.6 MB)
__device__ __half g_half[(size_t)MAXN * D];   // aggregated g, fp16 (25.6 MB)
__device__ __half wt16[D * D];                // [n][k] = W[k][n] fp16

// ---------------- smem layout for GEMM (bytes) ------------------------------
#define A_BYTES  (TILE_M * ROWP * 2)               //  5120
#define B_BYTES  (D * ROWP * 2)                    // 20480
#define OFF_A    0
#define OFF_B    (A_BYTES)
#define STAGE    (A_BYTES + B_BYTES)               // 25600
#define NSTAGE   3
#define OFF_PAR  (NSTAGE * STAGE)                  // 76800 : bias|gamma|beta
#define OFF_REDS (OFF_PAR + 3 * D * 4)             // 79872
#define OFF_RED2 (OFF_REDS + TILE_M * 4 * 4)       // 80896
#define SMEM_TOTAL (OFF_RED2 + TILE_M * 4 * 4)     // 81920  -> 2 CTAs/SM

// ---------------- helpers ---------------------------------------------------
__device__ __forceinline__ uint32_t smem_u32(const void* p) {
    uint32_t a;
    asm("{ .reg .u64 t; cvta.to.shared.u64 t, %1; cvt.u32.u64 %0, t; }"
        : "=r"(a) : "l"(p));
    return a;
}
__device__ __forceinline__ void cp16(uint32_t dst, const void* src, bool valid) {
    const int sz = valid ? 16 : 0;
    asm volatile("cp.async.cg.shared.global [%0], [%1], 16, %2;"
                 :: "r"(dst), "l"(src), "r"(sz));
}
__device__ __forceinline__ void ldm4(uint32_t* r, uint32_t addr) {
    asm volatile("ldmatrix.sync.aligned.m8n8.x4.shared.b16 {%0,%1,%2,%3}, [%4];"
                 : "=r"(r[0]), "=r"(r[1]), "=r"(r[2]), "=r"(r[3]) : "r"(addr));
}
__device__ __forceinline__ void mma_f16(float* c, const uint32_t* a,
                                        uint32_t b0, uint32_t b1) {
    asm volatile("mma.sync.aligned.m16n8k16.row.col.f32.f16.f16.f32 "
                 "{%0,%1,%2,%3}, {%4,%5,%6,%7}, {%8,%9}, {%0,%1,%2,%3};"
                 : "+f"(c[0]), "+f"(c[1]), "+f"(c[2]), "+f"(c[3])
                 : "r"(a[0]), "r"(a[1]), "r"(a[2]), "r"(a[3]), "r"(b0), "r"(b1));
}

// ---------------------------------------------------------------------------
// Kernel 0 (merged): blocks [0, nblk_feat) convert features fp32 -> fp16
// with 4 independent loads per thread (MLP=4 to saturate DRAM);
// blocks [nblk_feat, nblk_feat+64) transpose W -> fp16 [n][k].
// ---------------------------------------------------------------------------
__global__ __launch_bounds__(256) void prep_kernel(
    const float* __restrict__ feats,
    const float* __restrict__ W,
    int total4, int nblk_feat)
{
    __shared__ float s[32][33];
    const int b   = blockIdx.x;
    const int tid = threadIdx.x;

    if (b < nblk_feat) {
        const int i0 = b * 1024 + tid;
        float4 v[4];
        bool   ok[4];
#pragma unroll
        for (int j = 0; j < 4; j++) {
            const int i = i0 + j * 256;
            ok[j] = i < total4;
            if (ok[j]) v[j] = ((const float4*)feats)[i];
        }
#pragma unroll
        for (int j = 0; j < 4; j++) {
            if (!ok[j]) continue;
            const int i = i0 + j * 256;
            const __half2 a = __floats2half2_rn(v[j].x, v[j].y);
            const __half2 c = __floats2half2_rn(v[j].z, v[j].w);
            uint2 pk;
            pk.x = *(const uint32_t*)&a;
            pk.y = *(const uint32_t*)&c;
            *(uint2*)&feat16[(size_t)i * 4] = pk;
        }
    } else {
        const int bb = b - nblk_feat;             // 0..63
        const int n0 = (bb & 7) * 32, k0 = (bb >> 3) * 32;
        const int tx = tid & 31, ty = tid >> 5;   // 32 x 8
#pragma unroll
        for (int i = 0; i < 4; i++)
            s[ty + 8 * i][tx] = W[(size_t)(k0 + ty + 8 * i) * D + n0 + tx];
        __syncthreads();
#pragma unroll
        for (int i = 0; i < 4; i++) {
            const int nl = ty + 8 * i;
            wt16[(size_t)(n0 + nl) * D + k0 + tx] = __float2half_rn(s[tx][nl]);
        }
    }
}

// ---------------------------------------------------------------------------
// Kernel A: warp-per-node gather (no smem, no barriers).  Lane reads uint4
// (8 halves); weights/indices broadcast via shuffles.  [proven R10 version]
// ---------------------------------------------------------------------------
__global__ __launch_bounds__(256) void gather_kernel(
    const int* __restrict__ nbrs,
    const float* __restrict__ iw,
    int n)
{
    const int lane = threadIdx.x & 31;
    const int node = blockIdx.x * 8 + (threadIdx.x >> 5);
    if (node >= n) return;   // warp-uniform

    float w = 0.f;
    int   ix = 0;
    if (lane < KNBR) {
        w  = iw[(size_t)node * KNBR + lane];
        ix = nbrs[(size_t)node * KNBR + lane];
        ix = ix < 0 ? 0 : (ix >= n ? n - 1 : ix);
    }
    float wsum = w;
#pragma unroll
    for (int o = 16; o; o >>= 1) wsum += __shfl_xor_sync(0xffffffffu, wsum, o);
    const bool zero = (wsum == 0.f);
    const float inv = zero ? 0.f : 1.0f / wsum;

    const uint4* fp = (const uint4*)feat16;
    float acc[8];
#pragma unroll
    for (int j = 0; j < 8; j++) acc[j] = 0.f;

#pragma unroll
    for (int k = 0; k < KNBR; k++) {
        const float wr = __shfl_sync(0xffffffffu, w,  k);
        const int   ir = __shfl_sync(0xffffffffu, ix, k);
        const float wk = zero ? (1.0f / KNBR) : wr * inv;
        const uint4 raw = fp[(size_t)ir * (D / 8) + lane];
        const __half2* h = (const __half2*)&raw;
#pragma unroll
        for (int j = 0; j < 4; j++) {
            const float2 f = __half22float2(h[j]);
            acc[2 * j]     = fmaf(wk, f.x, acc[2 * j]);
            acc[2 * j + 1] = fmaf(wk, f.y, acc[2 * j + 1]);
        }
    }

    uint4 o;
    {
        const __half2 p0 = __floats2half2_rn(acc[0], acc[1]);
        const __half2 p1 = __floats2half2_rn(acc[2], acc[3]);
        const __half2 p2 = __floats2half2_rn(acc[4], acc[5]);
        const __half2 p3 = __floats2half2_rn(acc[6], acc[7]);
        o.x = *(const uint32_t*)&p0;
        o.y = *(const uint32_t*)&p1;
        o.z = *(const uint32_t*)&p2;
        o.w = *(const uint32_t*)&p3;
    }
    *(uint4*)&g_half[(size_t)node * D + lane * 8] = o;
}

// ---------------------------------------------------------------------------
// Kernel B: fp16 GEMM via mma.sync (m16n8k16), single pass,
// tile 64x256, K in 8 chunks of 32, 3-stage cp.async pipeline, fused LN.
// 2 CTAs/SM (82 KB smem, regs capped at 128).
// ---------------------------------------------------------------------------
__global__ __launch_bounds__(256, 2) void gemm_ln_mma_kernel(
    const float* __restrict__ bias,
    const float* __restrict__ gamma,
    const float* __restrict__ beta,
    float* __restrict__ out, int n)
{
    extern __shared__ char smem[];
    const uint32_t sb = smem_u32(smem);
    const int tid  = threadIdx.x;
    const int lane = tid & 31;
    const int wid  = tid >> 5;
    const int wm   = wid & 1;
    const int wn   = wid >> 1;
    const int m0   = blockIdx.x * TILE_M;

    {
        float* p = (float*)(smem + OFF_PAR);
        for (int i = tid; i < D; i += 256) {
            p[i]         = bias[i];
            p[D + i]     = gamma[i];
            p[2 * D + i] = beta[i];
        }
    }

    float acc[2][8][4];
#pragma unroll
    for (int t = 0; t < 2; t++)
#pragma unroll
        for (int j = 0; j < 8; j++)
#pragma unroll
            for (int q = 0; q < 4; q++) acc[t][j][q] = 0.f;

    const uint32_t a_lane = (uint32_t)(lane & 15) * (ROWP * 2) + (uint32_t)(lane >> 4) * 16;
    const uint32_t b_lane = (uint32_t)((lane & 7) + ((lane >> 4) << 3)) * (ROWP * 2)
                          + (uint32_t)((lane >> 3) & 1) * 16;

    auto load_stage = [&](int st, int c) {
        const int k0 = c * KCH;
        const uint32_t base = sb + (uint32_t)st * STAGE;
        // A: 64 rows x 4 chunks(16B) = 256 cp16 -> 1/thread
        {
            const int r  = tid >> 2;           // 0..63
            const int c8 = tid & 3;            // 0..3
            const int grow = m0 + r;
            const bool valid = grow < n;
            const int gr = valid ? grow : 0;
            const __half* src = g_half + (size_t)gr * D + k0 + c8 * 8;
            cp16(base + OFF_A + (uint32_t)r * (ROWP * 2) + (uint32_t)c8 * 16, src, valid);
        }
        // B: 256 rows x 4 chunks = 1024 cp16 -> 4/thread
#pragma unroll
        for (int i = 0; i < 4; i++) {
            const int idx = tid + i * 256;     // 0..1023
            const int r  = idx >> 2;           // 0..255
            const int c8 = idx & 3;            // 0..3
            const __half* src = wt16 + (size_t)r * D + k0 + c8 * 8;
            cp16(base + OFF_B + (uint32_t)r * (ROWP * 2) + (uint32_t)c8 * 16, src, true);
        }
        asm volatile("cp.async.commit_group;");
    };

    load_stage(0, 0);
    load_stage(1, 1);

#pragma unroll
    for (int c = 0; c < NCH; c++) {
        if (c + 2 < NCH) {
            load_stage((c + 2) % NSTAGE, c + 2);
            asm volatile("cp.async.wait_group 2;");
        } else if (c + 1 < NCH) {
            asm volatile("cp.async.wait_group 1;");
        } else {
            asm volatile("cp.async.wait_group 0;");
        }
        __syncthreads();

        const uint32_t base = sb + (uint32_t)(c % NSTAGE) * STAGE;
#pragma unroll
        for (int ks = 0; ks < 2; ks++) {
            uint32_t ah[2][4], bh[4][4];
#pragma unroll
            for (int t = 0; t < 2; t++) {
                const uint32_t ao = base + OFF_A
                                  + (uint32_t)(wm * 32 + t * 16) * (ROWP * 2)
                                  + (uint32_t)ks * 32 + a_lane;
                ldm4(ah[t], ao);
            }
#pragma unroll
            for (int p = 0; p < 4; p++) {
                const uint32_t bo = base + OFF_B
                                  + (uint32_t)(wn * 64 + p * 16) * (ROWP * 2)
                                  + (uint32_t)ks * 32 + b_lane;
                ldm4(bh[p], bo);
            }
#pragma unroll
            for (int t = 0; t < 2; t++)
#pragma unroll
                for (int j = 0; j < 8; j++)
                    mma_f16(acc[t][j], ah[t],
                            bh[j >> 1][(j & 1) * 2], bh[j >> 1][(j & 1) * 2 + 1]);
        }
        __syncthreads();
    }

    // ---------------- fused LayerNorm epilogue -----------------------------
    const float* bias_s = (const float*)(smem + OFF_PAR);
    const float* gam_s  = bias_s + D;
    const float* bet_s  = bias_s + 2 * D;

    float s[4]  = {0.f, 0.f, 0.f, 0.f};
    float s2[4] = {0.f, 0.f, 0.f, 0.f};
#pragma unroll
    for (int t = 0; t < 2; t++)
#pragma unroll
        for (int j = 0; j < 8; j++)
#pragma unroll
            for (int q = 0; q < 4; q++) {
                const int col = wn * 64 + j * 8 + (lane & 3) * 2 + (q & 1);
                const float v = acc[t][j][q] + bias_s[col];
                acc[t][j][q] = v;
                const int slot = t * 2 + (q >> 1);
                s[slot] += v;
                s2[slot] = fmaf(v, v, s2[slot]);
            }
#pragma unroll
    for (int slot = 0; slot < 4; slot++) {
        s[slot]  += __shfl_xor_sync(0xffffffffu, s[slot], 1);
        s2[slot] += __shfl_xor_sync(0xffffffffu, s2[slot], 1);
        s[slot]  += __shfl_xor_sync(0xffffffffu, s[slot], 2);
        s2[slot] += __shfl_xor_sync(0xffffffffu, s2[slot], 2);
    }
    float* redS  = (float*)(smem + OFF_REDS);
    float* redS2 = (float*)(smem + OFF_RED2);
    if ((lane & 3) == 0) {
#pragma unroll
        for (int slot = 0; slot < 4; slot++) {
            const int row = wm * 32 + (slot >> 1) * 16 + (slot & 1) * 8 + (lane >> 2);
            redS[row * 4 + wn]  = s[slot];
            redS2[row * 4 + wn] = s2[slot];
        }
    }
    __syncthreads();

#pragma unroll
    for (int slot = 0; slot < 4; slot++) {
        const int row = wm * 32 + (slot >> 1) * 16 + (slot & 1) * 8 + (lane >> 2);
        const float S  = redS[row * 4 + 0] + redS[row * 4 + 1]
                       + redS[row * 4 + 2] + redS[row * 4 + 3];
        const float Q  = redS2[row * 4 + 0] + redS2[row * 4 + 1]
                       + redS2[row * 4 + 2] + redS2[row * 4 + 3];
        const float mean = S * (1.0f / D);
        const float var  = fmaxf(Q * (1.0f / D) - mean * mean, 0.f);
        const float rstd = rsqrtf(var + LN_EPS);
        const int gr = m0 + row;
        if (gr < n) {
            const int t = slot >> 1, h = slot & 1;
#pragma unroll
            for (int j = 0; j < 8; j++) {
                const int col = wn * 64 + j * 8 + (lane & 3) * 2;
                float2 o;
                o.x = (acc[t][j][h * 2 + 0] - mean) * rstd * gam_s[col]     + bet_s[col];
                o.y = (acc[t][j][h * 2 + 1] - mean) * rstd * gam_s[col + 1] + bet_s[col + 1];
                *(float2*)&out[(size_t)gr * D + col] = o;
            }
        }
    }
}

// ---------------------------------------------------------------------------
extern "C" void kernel_launch(void* const* d_in, const int* in_sizes, int n_in,
                              void* d_out, int out_size)
{
    const float* feats = (const float*)d_in[0];
    const int*   nbrs  = (const int*)d_in[1];
    const float* iw    = (const float*)d_in[2];
    const float* Wm    = (const float*)d_in[3];
    const float* bias  = (const float*)d_in[4];
    const float* gam   = (const float*)d_in[5];
    const float* bet   = (const float*)d_in[6];
    float*       out   = (float*)d_out;

    const int n = in_sizes[0] / D;   // 50000

    cudaFuncSetAttribute(gemm_ln_mma_kernel,
                         cudaFuncAttributeMaxDynamicSharedMemorySize, SMEM_TOTAL);

    const int total4    = n * (D / 4);
    const int nblk_feat = (total4 + 1023) / 1024;
    prep_kernel<<<nblk_feat + 64, 256>>>(feats, Wm, total4, nblk_feat);
    gather_kernel<<<(n + 7) / 8, 256>>>(nbrs, iw, n);
    gemm_ln_mma_kernel<<<(n + TILE_M - 1) / TILE_M, 256, SMEM_TOTAL>>>(bias, gam, bet, out, n);
}

// round 15
// speedup vs baseline: 1.0357x; 1.0357x over previous
#include <cuda_runtime.h>
#include <cuda_fp16.h>
#include <cstdint>

#define D       256
#define KNBR    16
#define MAXN    50000
#define LN_EPS  1e-5f
#define TILE_M  64
#define KCH     64
#define ROWP    72      // padded row pitch in fp16 elems (144 B) -> conflict-free ldmatrix

// ---------------- scratch (static device arrays; no allocations) ------------
__device__ __half feat16[(size_t)MAXN * D];   // fp16 features (25.6 MB)
__device__ __half g_half[(size_t)MAXN * D];   // aggregated g, fp16 (25.6 MB)
__device__ __half wt16[D * D];                // [n][k] = W[k][n] fp16

// ---------------- smem layout for GEMM (bytes) ------------------------------
#define A_BYTES  (TILE_M * ROWP * 2)               //  9216
#define B_BYTES  (D * ROWP * 2)                    // 36864
#define OFF_A    0
#define OFF_B    (A_BYTES)
#define STAGE    (A_BYTES + B_BYTES)               // 46080
#define OFF_PAR  (2 * STAGE)                       // 92160 : bias|gamma|beta
#define OFF_REDS (OFF_PAR + 3 * D * 4)             // 95232
#define OFF_RED2 (OFF_REDS + TILE_M * 4 * 4)       // 96256
#define SMEM_TOTAL (OFF_RED2 + TILE_M * 4 * 4)     // 97280  -> 2 CTAs/SM

// ---------------- helpers ---------------------------------------------------
__device__ __forceinline__ uint32_t smem_u32(const void* p) {
    uint32_t a;
    asm("{ .reg .u64 t; cvta.to.shared.u64 t, %1; cvt.u32.u64 %0, t; }"
        : "=r"(a) : "l"(p));
    return a;
}
__device__ __forceinline__ void cp16(uint32_t dst, const void* src, bool valid) {
    const int sz = valid ? 16 : 0;
    asm volatile("cp.async.cg.shared.global [%0], [%1], 16, %2;"
                 :: "r"(dst), "l"(src), "r"(sz));
}
__device__ __forceinline__ void ldm4(uint32_t* r, uint32_t addr) {
    asm volatile("ldmatrix.sync.aligned.m8n8.x4.shared.b16 {%0,%1,%2,%3}, [%4];"
                 : "=r"(r[0]), "=r"(r[1]), "=r"(r[2]), "=r"(r[3]) : "r"(addr));
}
__device__ __forceinline__ void mma_f16(float* c, const uint32_t* a,
                                        uint32_t b0, uint32_t b1) {
    asm volatile("mma.sync.aligned.m16n8k16.row.col.f32.f16.f16.f32 "
                 "{%0,%1,%2,%3}, {%4,%5,%6,%7}, {%8,%9}, {%0,%1,%2,%3};"
                 : "+f"(c[0]), "+f"(c[1]), "+f"(c[2]), "+f"(c[3])
                 : "r"(a[0]), "r"(a[1]), "r"(a[2]), "r"(a[3]), "r"(b0), "r"(b1));
}

// ---------------------------------------------------------------------------
// Kernel 0 (merged): blocks [0, nblk_feat) convert features fp32 -> fp16
// with 4 independent loads per thread (MLP=4);
// blocks [nblk_feat, nblk_feat+64) transpose W -> fp16 [n][k].
// [proven R13 version]
// ---------------------------------------------------------------------------
__global__ __launch_bounds__(256) void prep_kernel(
    const float* __restrict__ feats,
    const float* __restrict__ W,
    int total4, int nblk_feat)
{
    __shared__ float s[32][33];
    const int b   = blockIdx.x;
    const int tid = threadIdx.x;

    if (b < nblk_feat) {
        const int i0 = b * 1024 + tid;
        float4 v[4];
        bool   ok[4];
#pragma unroll
        for (int j = 0; j < 4; j++) {
            const int i = i0 + j * 256;
            ok[j] = i < total4;
            if (ok[j]) v[j] = ((const float4*)feats)[i];
        }
#pragma unroll
        for (int j = 0; j < 4; j++) {
            if (!ok[j]) continue;
            const int i = i0 + j * 256;
            const __half2 a = __floats2half2_rn(v[j].x, v[j].y);
            const __half2 c = __floats2half2_rn(v[j].z, v[j].w);
            uint2 pk;
            pk.x = *(const uint32_t*)&a;
            pk.y = *(const uint32_t*)&c;
            *(uint2*)&feat16[(size_t)i * 4] = pk;
        }
    } else {
        const int bb = b - nblk_feat;             // 0..63
        const int n0 = (bb & 7) * 32, k0 = (bb >> 3) * 32;
        const int tx = tid & 31, ty = tid >> 5;   // 32 x 8
#pragma unroll
        for (int i = 0; i < 4; i++)
            s[ty + 8 * i][tx] = W[(size_t)(k0 + ty + 8 * i) * D + n0 + tx];
        __syncthreads();
#pragma unroll
        for (int i = 0; i < 4; i++) {
            const int nl = ty + 8 * i;
            wt16[(size_t)(n0 + nl) * D + k0 + tx] = __float2half_rn(s[tx][nl]);
        }
    }
}

// ---------------------------------------------------------------------------
// Kernel A: warp-per-node gather (no smem, no barriers).  Lane reads uint4
// (8 halves); weights/indices broadcast via shuffles.  [proven R10 version]
// ---------------------------------------------------------------------------
__global__ __launch_bounds__(256) void gather_kernel(
    const int* __restrict__ nbrs,
    const float* __restrict__ iw,
    int n)
{
    const int lane = threadIdx.x & 31;
    const int node = blockIdx.x * 8 + (threadIdx.x >> 5);
    if (node >= n) return;   // warp-uniform

    float w = 0.f;
    int   ix = 0;
    if (lane < KNBR) {
        w  = iw[(size_t)node * KNBR + lane];
        ix = nbrs[(size_t)node * KNBR + lane];
        ix = ix < 0 ? 0 : (ix >= n ? n - 1 : ix);
    }
    float wsum = w;
#pragma unroll
    for (int o = 16; o; o >>= 1) wsum += __shfl_xor_sync(0xffffffffu, wsum, o);
    const bool zero = (wsum == 0.f);
    const float inv = zero ? 0.f : 1.0f / wsum;

    const uint4* fp = (const uint4*)feat16;
    float acc[8];
#pragma unroll
    for (int j = 0; j < 8; j++) acc[j] = 0.f;

#pragma unroll
    for (int k = 0; k < KNBR; k++) {
        const float wr = __shfl_sync(0xffffffffu, w,  k);
        const int   ir = __shfl_sync(0xffffffffu, ix, k);
        const float wk = zero ? (1.0f / KNBR) : wr * inv;
        const uint4 raw = fp[(size_t)ir * (D / 8) + lane];
        const __half2* h = (const __half2*)&raw;
#pragma unroll
        for (int j = 0; j < 4; j++) {
            const float2 f = __half22float2(h[j]);
            acc[2 * j]     = fmaf(wk, f.x, acc[2 * j]);
            acc[2 * j + 1] = fmaf(wk, f.y, acc[2 * j + 1]);
        }
    }

    uint4 o;
    {
        const __half2 p0 = __floats2half2_rn(acc[0], acc[1]);
        const __half2 p1 = __floats2half2_rn(acc[2], acc[3]);
        const __half2 p2 = __floats2half2_rn(acc[4], acc[5]);
        const __half2 p3 = __floats2half2_rn(acc[6], acc[7]);
        o.x = *(const uint32_t*)&p0;
        o.y = *(const uint32_t*)&p1;
        o.z = *(const uint32_t*)&p2;
        o.w = *(const uint32_t*)&p3;
    }
    *(uint4*)&g_half[(size_t)node * D + lane * 8] = o;
}

// ---------------------------------------------------------------------------
// Kernel B: fp16 GEMM via mma.sync (m16n8k16), single pass,
// tile 64x256, K in 4 chunks of 64, 2-stage cp.async double-buffering,
// fused LN.  2 CTAs/SM (97 KB smem, regs capped at 128).  [proven R8 version]
// ---------------------------------------------------------------------------
__global__ __launch_bounds__(256, 2) void gemm_ln_mma_kernel(
    const float* __restrict__ bias,
    const float* __restrict__ gamma,
    const float* __restrict__ beta,
    float* __restrict__ out, int n)
{
    extern __shared__ char smem[];
    const uint32_t sb = smem_u32(smem);
    const int tid  = threadIdx.x;
    const int lane = tid & 31;
    const int wid  = tid >> 5;
    const int wm   = wid & 1;
    const int wn   = wid >> 1;
    const int m0   = blockIdx.x * TILE_M;

    {
        float* p = (float*)(smem + OFF_PAR);
        for (int i = tid; i < D; i += 256) {
            p[i]         = bias[i];
            p[D + i]     = gamma[i];
            p[2 * D + i] = beta[i];
        }
    }

    float acc[2][8][4];
#pragma unroll
    for (int t = 0; t < 2; t++)
#pragma unroll
        for (int j = 0; j < 8; j++)
#pragma unroll
            for (int q = 0; q < 4; q++) acc[t][j][q] = 0.f;

    const uint32_t a_lane = (uint32_t)(lane & 15) * (ROWP * 2) + (uint32_t)(lane >> 4) * 16;
    const uint32_t b_lane = (uint32_t)((lane & 7) + ((lane >> 4) << 3)) * (ROWP * 2)
                          + (uint32_t)((lane >> 3) & 1) * 16;

    auto load_stage = [&](int st, int c) {
        const int k0 = c * KCH;
        const uint32_t base = sb + st * STAGE;
#pragma unroll
        for (int i = 0; i < 2; i++) {
            const int idx = tid + i * 256;
            const int r  = idx >> 3;
            const int c8 = idx & 7;
            const int grow = m0 + r;
            const bool valid = grow < n;
            const int gr = valid ? grow : 0;
            const __half* src = g_half + (size_t)gr * D + k0 + c8 * 8;
            cp16(base + OFF_A + (uint32_t)r * (ROWP * 2) + (uint32_t)c8 * 16, src, valid);
        }
#pragma unroll
        for (int i = 0; i < 8; i++) {
            const int idx = tid + i * 256;
            const int r  = idx >> 3;
            const int c8 = idx & 7;
            const __half* src = wt16 + (size_t)r * D + k0 + c8 * 8;
            cp16(base + OFF_B + (uint32_t)r * (ROWP * 2) + (uint32_t)c8 * 16, src, true);
        }
        asm volatile("cp.async.commit_group;");
    };

    load_stage(0, 0);

#pragma unroll
    for (int c = 0; c < 4; c++) {
        if (c < 3) {
            load_stage((c + 1) & 1, c + 1);
            asm volatile("cp.async.wait_group 1;");
        } else {
            asm volatile("cp.async.wait_group 0;");
        }
        __syncthreads();

        const uint32_t base = sb + (uint32_t)(c & 1) * STAGE;
#pragma unroll
        for (int ks = 0; ks < 4; ks++) {
            uint32_t ah[2][4], bh[4][4];
#pragma unroll
            for (int t = 0; t < 2; t++) {
                const uint32_t ao = base + OFF_A
                                  + (uint32_t)(wm * 32 + t * 16) * (ROWP * 2)
                                  + (uint32_t)ks * 32 + a_lane;
                ldm4(ah[t], ao);
            }
#pragma unroll
            for (int p = 0; p < 4; p++) {
                const uint32_t bo = base + OFF_B
                                  + (uint32_t)(wn * 64 + p * 16) * (ROWP * 2)
                                  + (uint32_t)ks * 32 + b_lane;
                ldm4(bh[p], bo);
            }
#pragma unroll
            for (int t = 0; t < 2; t++)
#pragma unroll
                for (int j = 0; j < 8; j++)
                    mma_f16(acc[t][j], ah[t],
                            bh[j >> 1][(j & 1) * 2], bh[j >> 1][(j & 1) * 2 + 1]);
        }
        __syncthreads();
    }

    // ---------------- fused LayerNorm epilogue -----------------------------
    const float* bias_s = (const float*)(smem + OFF_PAR);
    const float* gam_s  = bias_s + D;
    const float* bet_s  = bias_s + 2 * D;

    float s[4]  = {0.f, 0.f, 0.f, 0.f};
    float s2[4] = {0.f, 0.f, 0.f, 0.f};
#pragma unroll
    for (int t = 0; t < 2; t++)
#pragma unroll
        for (int j = 0; j < 8; j++)
#pragma unroll
            for (int q = 0; q < 4; q++) {
                const int col = wn * 64 + j * 8 + (lane & 3) * 2 + (q & 1);
                const float v = acc[t][j][q] + bias_s[col];
                acc[t][j][q] = v;
                const int slot = t * 2 + (q >> 1);
                s[slot] += v;
                s2[slot] = fmaf(v, v, s2[slot]);
            }
#pragma unroll
    for (int slot = 0; slot < 4; slot++) {
        s[slot]  += __shfl_xor_sync(0xffffffffu, s[slot], 1);
        s2[slot] += __shfl_xor_sync(0xffffffffu, s2[slot], 1);
        s[slot]  += __shfl_xor_sync(0xffffffffu, s[slot], 2);
        s2[slot] += __shfl_xor_sync(0xffffffffu, s2[slot], 2);
    }
    float* redS  = (float*)(smem + OFF_REDS);
    float* redS2 = (float*)(smem + OFF_RED2);
    if ((lane & 3) == 0) {
#pragma unroll
        for (int slot = 0; slot < 4; slot++) {
            const int row = wm * 32 + (slot >> 1) * 16 + (slot & 1) * 8 + (lane >> 2);
            redS[row * 4 + wn]  = s[slot];
            redS2[row * 4 + wn] = s2[slot];
        }
    }
    __syncthreads();

#pragma unroll
    for (int slot = 0; slot < 4; slot++) {
        const int row = wm * 32 + (slot >> 1) * 16 + (slot & 1) * 8 + (lane >> 2);
        const float S  = redS[row * 4 + 0] + redS[row * 4 + 1]
                       + redS[row * 4 + 2] + redS[row * 4 + 3];
        const float Q  = redS2[row * 4 + 0] + redS2[row * 4 + 1]
                       + redS2[row * 4 + 2] + redS2[row * 4 + 3];
        const float mean = S * (1.0f / D);
        const float var  = fmaxf(Q * (1.0f / D) - mean * mean, 0.f);
        const float rstd = rsqrtf(var + LN_EPS);
        const int gr = m0 + row;
        if (gr < n) {
            const int t = slot >> 1, h = slot & 1;
#pragma unroll
            for (int j = 0; j < 8; j++) {
                const int col = wn * 64 + j * 8 + (lane & 3) * 2;
                float2 o;
                o.x = (acc[t][j][h * 2 + 0] - mean) * rstd * gam_s[col]     + bet_s[col];
                o.y = (acc[t][j][h * 2 + 1] - mean) * rstd * gam_s[col + 1] + bet_s[col + 1];
                *(float2*)&out[(size_t)gr * D + col] = o;
            }
        }
    }
}

// ---------------------------------------------------------------------------
extern "C" void kernel_launch(void* const* d_in, const int* in_sizes, int n_in,
                              void* d_out, int out_size)
{
    const float* feats = (const float*)d_in[0];
    const int*   nbrs  = (const int*)d_in[1];
    const float* iw    = (const float*)d_in[2];
    const float* Wm    = (const float*)d_in[3];
    const float* bias  = (const float*)d_in[4];
    const float* gam   = (const float*)d_in[5];
    const float* bet   = (const float*)d_in[6];
    float*       out   = (float*)d_out;

    const int n = in_sizes[0] / D;   // 50000

    cudaFuncSetAttribute(gemm_ln_mma_kernel,
                         cudaFuncAttributeMaxDynamicSharedMemorySize, SMEM_TOTAL);

    const int total4    = n * (D / 4);
    const int nblk_feat = (total4 + 1023) / 1024;
    prep_kernel<<<nblk_feat + 64, 256>>>(feats, Wm, total4, nblk_feat);
    gather_kernel<<<(n + 7) / 8, 256>>>(nbrs, iw, n);
    gemm_ln_mma_kernel<<<(n + TILE_M - 1) / TILE_M, 256, SMEM_TOTAL>>>(bias, gam, bet, out, n);
}